// round 1
// baseline (speedup 1.0000x reference)
#include <cuda_runtime.h>
#include <cstdint>

// STN flow-relative bilinear warp.
// x: [1, C, H, W] f32, flow: [1, 2, H, W] f32 (pixel displacements)
// out[c, y, x] = bilinear_sample(x[c], x + flow_x, y + flow_y) with zero padding,
// align_corners=False normalization round-trip (matches reference exactly).

static constexpr int H  = 1024;
static constexpr int W  = 1024;
static constexpr int C  = 32;
static constexpr int HW = H * W;

__global__ __launch_bounds__(256) void warp_bilinear_kernel(
    const float* __restrict__ flow,
    const float* __restrict__ x,
    float* __restrict__ out)
{
    int p = blockIdx.x * blockDim.x + threadIdx.x;
    if (p >= HW) return;

    int px = p & (W - 1);
    int py = p >> 10;          // W == 1024

    float fx = flow[p];
    float fy = flow[HW + p];

    // Match reference math: gx = (fx+px)/(W-1)*2 - 1 ; ix = ((gx+1)*W - 1)*0.5
    float gx = (fx + (float)px) * (2.0f / (float)(W - 1)) - 1.0f;
    float gy = (fy + (float)py) * (2.0f / (float)(H - 1)) - 1.0f;
    float ix = ((gx + 1.0f) * (float)W - 1.0f) * 0.5f;
    float iy = ((gy + 1.0f) * (float)H - 1.0f) * 0.5f;

    float x0f = floorf(ix);
    float y0f = floorf(iy);
    float wx1 = ix - x0f;
    float wy1 = iy - y0f;
    float wx0 = 1.0f - wx1;
    float wy0 = 1.0f - wy1;

    int x0 = (int)x0f;
    int y0 = (int)y0f;
    int x1 = x0 + 1;
    int y1 = y0 + 1;

    // zero-padding validity folded into weights (input has no NaN/Inf)
    float vx0 = (x0 >= 0 && x0 < W) ? 1.0f : 0.0f;
    float vx1 = (x1 >= 0 && x1 < W) ? 1.0f : 0.0f;
    float vy0 = (y0 >= 0 && y0 < H) ? 1.0f : 0.0f;
    float vy1 = (y1 >= 0 && y1 < H) ? 1.0f : 0.0f;

    int cx0 = min(max(x0, 0), W - 1);
    int cx1 = min(max(x1, 0), W - 1);
    int cy0 = min(max(y0, 0), H - 1);
    int cy1 = min(max(y1, 0), H - 1);

    float w00 = wx0 * wy0 * vx0 * vy0;
    float w10 = wx1 * wy0 * vx1 * vy0;
    float w01 = wx0 * wy1 * vx0 * vy1;
    float w11 = wx1 * wy1 * vx1 * vy1;

    int o00 = cy0 * W + cx0;
    int o10 = cy0 * W + cx1;
    int o01 = cy1 * W + cx0;
    int o11 = cy1 * W + cx1;

    const float* xp = x;
    float* op = out + p;

#pragma unroll
    for (int c = 0; c < C; ++c) {
        float v = w00 * __ldg(xp + o00)
                + w10 * __ldg(xp + o10)
                + w01 * __ldg(xp + o01)
                + w11 * __ldg(xp + o11);
        op[(size_t)c * HW] = v;
        xp += HW;
    }
}

extern "C" void kernel_launch(void* const* d_in, const int* in_sizes, int n_in,
                              void* d_out, int out_size)
{
    const float* flow = (const float*)d_in[0];   // [1,2,H,W]
    const float* x    = (const float*)d_in[1];   // [1,C,H,W]
    float* out        = (float*)d_out;           // [1,C,H,W]

    (void)in_sizes; (void)n_in; (void)out_size;

    dim3 block(256);
    dim3 grid((HW + 255) / 256);
    warp_bilinear_kernel<<<grid, block>>>(flow, x, out);
}

// round 2
// speedup vs baseline: 1.3690x; 1.3690x over previous
#include <cuda_runtime.h>
#include <cstdint>

// STN flow-relative bilinear warp, two-pass:
//   pass 1: transpose x NCHW -> NHWC scratch (channels contiguous per pixel)
//   pass 2: per output pixel, gather 4 corner "channel lines" (128B each,
//           fully contiguous) and blend; store NCHW coalesced.

static constexpr int H  = 1024;
static constexpr int W  = 1024;
static constexpr int C  = 32;
static constexpr int HW = H * W;

// 128 MB scratch: x transposed to [H*W][C]
__device__ float g_xt[(size_t)HW * C];

// ---------------- pass 1: NCHW -> NHWC transpose ----------------
// Tile: 32 channels x 32 pixels. block(32,8), 4 row-iterations.
__global__ __launch_bounds__(256) void transpose_kernel(const float* __restrict__ x)
{
    __shared__ float tile[32][33];

    int p0 = blockIdx.x * 32;          // base pixel of this tile
    int tx = threadIdx.x;              // 0..31
    int ty = threadIdx.y;              // 0..7

#pragma unroll
    for (int i = 0; i < 4; ++i) {
        int c = ty + i * 8;
        // read: fixed channel, 32 consecutive pixels -> coalesced 128B
        tile[c][tx] = x[(size_t)c * HW + p0 + tx];
    }
    __syncthreads();

#pragma unroll
    for (int i = 0; i < 4; ++i) {
        int r = ty + i * 8;            // pixel within tile
        // write: fixed pixel, 32 consecutive channels -> coalesced 128B
        g_xt[(size_t)(p0 + r) * C + tx] = tile[tx][r];
    }
}

// ---------------- pass 2: bilinear warp from NHWC ----------------
__global__ __launch_bounds__(256) void warp_bilinear_nhwc_kernel(
    const float* __restrict__ flow,
    float* __restrict__ out)
{
    int p = blockIdx.x * blockDim.x + threadIdx.x;
    if (p >= HW) return;

    int px = p & (W - 1);
    int py = p >> 10;                  // W == 1024

    float fx = flow[p];
    float fy = flow[HW + p];

    // Match reference math exactly (normalize + unnormalize round-trip)
    float gx = (fx + (float)px) * (2.0f / (float)(W - 1)) - 1.0f;
    float gy = (fy + (float)py) * (2.0f / (float)(H - 1)) - 1.0f;
    float ix = ((gx + 1.0f) * (float)W - 1.0f) * 0.5f;
    float iy = ((gy + 1.0f) * (float)H - 1.0f) * 0.5f;

    float x0f = floorf(ix);
    float y0f = floorf(iy);
    float wx1 = ix - x0f;
    float wy1 = iy - y0f;
    float wx0 = 1.0f - wx1;
    float wy0 = 1.0f - wy1;

    int x0 = (int)x0f;
    int y0 = (int)y0f;
    int x1 = x0 + 1;
    int y1 = y0 + 1;

    // zero-padding validity folded into weights
    float vx0 = (x0 >= 0 && x0 < W) ? 1.0f : 0.0f;
    float vx1 = (x1 >= 0 && x1 < W) ? 1.0f : 0.0f;
    float vy0 = (y0 >= 0 && y0 < H) ? 1.0f : 0.0f;
    float vy1 = (y1 >= 0 && y1 < H) ? 1.0f : 0.0f;

    int cx0 = min(max(x0, 0), W - 1);
    int cx1 = min(max(x1, 0), W - 1);
    int cy0 = min(max(y0, 0), H - 1);
    int cy1 = min(max(y1, 0), H - 1);

    float w00 = wx0 * wy0 * vx0 * vy0;
    float w10 = wx1 * wy0 * vx1 * vy0;
    float w01 = wx0 * wy1 * vx0 * vy1;
    float w11 = wx1 * wy1 * vx1 * vy1;

    // channel-contiguous corner base pointers (each points at 128B line)
    const float4* r00 = (const float4*)(g_xt + (size_t)(cy0 * W + cx0) * C);
    const float4* r10 = (const float4*)(g_xt + (size_t)(cy0 * W + cx1) * C);
    const float4* r01 = (const float4*)(g_xt + (size_t)(cy1 * W + cx0) * C);
    const float4* r11 = (const float4*)(g_xt + (size_t)(cy1 * W + cx1) * C);

    float* op = out + p;

#pragma unroll
    for (int g = 0; g < C / 4; ++g) {
        float4 a = __ldg(r00 + g);
        float4 b = __ldg(r10 + g);
        float4 c = __ldg(r01 + g);
        float4 d = __ldg(r11 + g);

        float v0 = w00 * a.x + w10 * b.x + w01 * c.x + w11 * d.x;
        float v1 = w00 * a.y + w10 * b.y + w01 * c.y + w11 * d.y;
        float v2 = w00 * a.z + w10 * b.z + w01 * c.z + w11 * d.z;
        float v3 = w00 * a.w + w10 * b.w + w01 * c.w + w11 * d.w;

        // NCHW scalar stores: same c across warp, consecutive p -> coalesced
        op[(size_t)(4 * g + 0) * HW] = v0;
        op[(size_t)(4 * g + 1) * HW] = v1;
        op[(size_t)(4 * g + 2) * HW] = v2;
        op[(size_t)(4 * g + 3) * HW] = v3;
    }
}

extern "C" void kernel_launch(void* const* d_in, const int* in_sizes, int n_in,
                              void* d_out, int out_size)
{
    const float* flow = (const float*)d_in[0];   // [1,2,H,W]
    const float* x    = (const float*)d_in[1];   // [1,C,H,W]
    float* out        = (float*)d_out;           // [1,C,H,W]

    (void)in_sizes; (void)n_in; (void)out_size;

    transpose_kernel<<<HW / 32, dim3(32, 8)>>>(x);
    warp_bilinear_nhwc_kernel<<<(HW + 255) / 256, 256>>>(flow, out);
}

// round 3
// speedup vs baseline: 2.0545x; 1.5007x over previous
#include <cuda_runtime.h>
#include <cstdint>

// STN flow-relative bilinear warp, two-pass:
//   pass 1: transpose x NCHW -> NHWC scratch
//   pass 2: cooperative gather: 8 lanes per pixel, each lane owns one float4
//           channel-group of each 128B corner line -> fully packed L1 wavefronts.

static constexpr int H  = 1024;
static constexpr int W  = 1024;
static constexpr int C  = 32;
static constexpr int HW = H * W;

// 128 MB scratch: x transposed to [H*W][C]
__device__ float g_xt[(size_t)HW * C];

// ---------------- pass 1: NCHW -> NHWC transpose ----------------
__global__ __launch_bounds__(256) void transpose_kernel(const float* __restrict__ x)
{
    __shared__ float tile[32][33];

    int p0 = blockIdx.x * 32;
    int tx = threadIdx.x;              // 0..31
    int ty = threadIdx.y;              // 0..7

#pragma unroll
    for (int i = 0; i < 4; ++i) {
        int c = ty + i * 8;
        tile[c][tx] = x[(size_t)c * HW + p0 + tx];   // coalesced 128B read
    }
    __syncthreads();

#pragma unroll
    for (int i = 0; i < 4; ++i) {
        int r = ty + i * 8;
        g_xt[(size_t)(p0 + r) * C + tx] = tile[tx][r];  // coalesced 128B write
    }
}

// ---------------- pass 2: bilinear warp from NHWC ----------------
// Block = 256 threads = 32 pixels x 8 channel-groups.
// Warp 0 precomputes per-pixel corner offsets + weights into smem.
__global__ __launch_bounds__(256) void warp_bilinear_coop_kernel(
    const float* __restrict__ flow,
    float* __restrict__ out)
{
    __shared__ int   s_off[4][32];
    __shared__ float s_w[4][32];
    __shared__ float s_out[32][33];

    int tid = threadIdx.x;
    int p0  = blockIdx.x * 32;

    if (tid < 32) {
        int p  = p0 + tid;
        int px = p & (W - 1);
        int py = p >> 10;              // W == 1024

        float fx = flow[p];
        float fy = flow[HW + p];

        // Match reference math exactly (normalize + unnormalize round-trip)
        float gx = (fx + (float)px) * (2.0f / (float)(W - 1)) - 1.0f;
        float gy = (fy + (float)py) * (2.0f / (float)(H - 1)) - 1.0f;
        float ix = ((gx + 1.0f) * (float)W - 1.0f) * 0.5f;
        float iy = ((gy + 1.0f) * (float)H - 1.0f) * 0.5f;

        float x0f = floorf(ix);
        float y0f = floorf(iy);
        float wx1 = ix - x0f;
        float wy1 = iy - y0f;
        float wx0 = 1.0f - wx1;
        float wy0 = 1.0f - wy1;

        int x0 = (int)x0f;
        int y0 = (int)y0f;
        int x1 = x0 + 1;
        int y1 = y0 + 1;

        float vx0 = (x0 >= 0 && x0 < W) ? 1.0f : 0.0f;
        float vx1 = (x1 >= 0 && x1 < W) ? 1.0f : 0.0f;
        float vy0 = (y0 >= 0 && y0 < H) ? 1.0f : 0.0f;
        float vy1 = (y1 >= 0 && y1 < H) ? 1.0f : 0.0f;

        int cx0 = min(max(x0, 0), W - 1);
        int cx1 = min(max(x1, 0), W - 1);
        int cy0 = min(max(y0, 0), H - 1);
        int cy1 = min(max(y1, 0), H - 1);

        s_w[0][tid] = wx0 * wy0 * vx0 * vy0;
        s_w[1][tid] = wx1 * wy0 * vx1 * vy0;
        s_w[2][tid] = wx0 * wy1 * vx0 * vy1;
        s_w[3][tid] = wx1 * wy1 * vx1 * vy1;

        s_off[0][tid] = cy0 * W + cx0;
        s_off[1][tid] = cy0 * W + cx1;
        s_off[2][tid] = cy1 * W + cx0;
        s_off[3][tid] = cy1 * W + cx1;
    }
    __syncthreads();

    int pl = tid >> 3;                 // pixel within block (0..31)
    int cg = tid & 7;                  // channel-group (0..7), 4 floats each

    float a0 = 0.f, a1 = 0.f, a2 = 0.f, a3 = 0.f;
#pragma unroll
    for (int k = 0; k < 4; ++k) {
        const float4* line = (const float4*)(g_xt + (size_t)s_off[k][pl] * C);
        float4 v = __ldg(line + cg);   // 8 lanes cover one full 128B line
        float  w = s_w[k][pl];
        a0 += w * v.x;
        a1 += w * v.y;
        a2 += w * v.z;
        a3 += w * v.w;
    }

    int c0 = cg * 4;
    s_out[pl][c0 + 0] = a0;            // banks (pl + c) distinct -> conflict-free
    s_out[pl][c0 + 1] = a1;
    s_out[pl][c0 + 2] = a2;
    s_out[pl][c0 + 3] = a3;
    __syncthreads();

    // NCHW writeback: warp w handles channels 4w..4w+3, lanes = 32 pixels
    int lane = tid & 31;
    int wid  = tid >> 5;
#pragma unroll
    for (int i = 0; i < 4; ++i) {
        int c = wid * 4 + i;
        out[(size_t)c * HW + p0 + lane] = s_out[lane][c];  // coalesced 128B
    }
}

extern "C" void kernel_launch(void* const* d_in, const int* in_sizes, int n_in,
                              void* d_out, int out_size)
{
    const float* flow = (const float*)d_in[0];   // [1,2,H,W]
    const float* x    = (const float*)d_in[1];   // [1,C,H,W]
    float* out        = (float*)d_out;           // [1,C,H,W]

    (void)in_sizes; (void)n_in; (void)out_size;

    transpose_kernel<<<HW / 32, dim3(32, 8)>>>(x);
    warp_bilinear_coop_kernel<<<HW / 32, 256>>>(flow, out);
}

// round 4
// speedup vs baseline: 2.3764x; 1.1567x over previous
#include <cuda_runtime.h>
#include <cstdint>

// STN flow-relative bilinear warp, two-pass:
//   pass 1: NCHW -> NHWC transpose, float4 both sides, XOR-swizzled smem
//   pass 2: cooperative gather (8 lanes/pixel, 2 pixels/thread)

static constexpr int H  = 1024;
static constexpr int W  = 1024;
static constexpr int C  = 32;
static constexpr int HW = H * W;

// 128 MB scratch: x transposed to [H*W][C]
__device__ float g_xt[(size_t)HW * C];

// ---------------- pass 1: NCHW -> NHWC transpose ----------------
// Block: 256 threads, tile = 128 pixels x 32 channels.
// smem row per channel = 128 floats (512B); quad-swizzle: quad' = quad ^ (c>>2).
__device__ __forceinline__ int sw_addr(int c, int px) {
    return c * 128 + 4 * ((px >> 2) ^ (c >> 2)) + (px & 3);
}

__global__ __launch_bounds__(256) void transpose_kernel(const float* __restrict__ x)
{
    __shared__ float s[32 * 128];

    int tid = threadIdx.x;
    int p0  = blockIdx.x * 128;

    // phase 1: read NCHW as float4 (512B/warp coalesced), STS.128 swizzled
#pragma unroll
    for (int i = 0; i < 4; ++i) {
        int j   = i * 256 + tid;
        int c   = j >> 5;          // 0..31
        int pxg = j & 31;          // quad index 0..31
        float4 v = __ldcs((const float4*)(x + (size_t)c * HW + p0 + 4 * pxg));
        *(float4*)(s + c * 128 + 4 * (pxg ^ (c >> 2))) = v;
    }
    __syncthreads();

    // phase 2: gather 4 channels per thread (conflict-free), STG.128 NHWC
#pragma unroll
    for (int i = 0; i < 4; ++i) {
        int j  = i * 256 + tid;
        int pl = j >> 3;           // pixel 0..127
        int cg = j & 7;            // channel group 0..7
        float4 v;
        v.x = s[sw_addr(4 * cg + 0, pl)];
        v.y = s[sw_addr(4 * cg + 1, pl)];
        v.z = s[sw_addr(4 * cg + 2, pl)];
        v.w = s[sw_addr(4 * cg + 3, pl)];
        *(float4*)(g_xt + (size_t)(p0 + pl) * C + 4 * cg) = v;
    }
}

// ---------------- pass 2: bilinear warp from NHWC ----------------
// Block = 256 threads, 64 pixels. Each thread handles 2 pixels x 1 channel-group
// (4 floats) -> 8 independent LDG.128 chains.
__global__ __launch_bounds__(256) void warp_bilinear_coop_kernel(
    const float* __restrict__ flow,
    float* __restrict__ out)
{
    __shared__ int   s_off[4][64];
    __shared__ float s_w[4][64];
    __shared__ float s_out[64][33];

    int tid = threadIdx.x;
    int p0  = blockIdx.x * 64;

    if (tid < 64) {
        int p  = p0 + tid;
        int px = p & (W - 1);
        int py = p >> 10;              // W == 1024

        float fx = flow[p];
        float fy = flow[HW + p];

        // Match reference math exactly (normalize + unnormalize round-trip)
        float gx = (fx + (float)px) * (2.0f / (float)(W - 1)) - 1.0f;
        float gy = (fy + (float)py) * (2.0f / (float)(H - 1)) - 1.0f;
        float ix = ((gx + 1.0f) * (float)W - 1.0f) * 0.5f;
        float iy = ((gy + 1.0f) * (float)H - 1.0f) * 0.5f;

        float x0f = floorf(ix);
        float y0f = floorf(iy);
        float wx1 = ix - x0f;
        float wy1 = iy - y0f;
        float wx0 = 1.0f - wx1;
        float wy0 = 1.0f - wy1;

        int x0 = (int)x0f;
        int y0 = (int)y0f;
        int x1 = x0 + 1;
        int y1 = y0 + 1;

        float vx0 = (x0 >= 0 && x0 < W) ? 1.0f : 0.0f;
        float vx1 = (x1 >= 0 && x1 < W) ? 1.0f : 0.0f;
        float vy0 = (y0 >= 0 && y0 < H) ? 1.0f : 0.0f;
        float vy1 = (y1 >= 0 && y1 < H) ? 1.0f : 0.0f;

        int cx0 = min(max(x0, 0), W - 1);
        int cx1 = min(max(x1, 0), W - 1);
        int cy0 = min(max(y0, 0), H - 1);
        int cy1 = min(max(y1, 0), H - 1);

        s_w[0][tid] = wx0 * wy0 * vx0 * vy0;
        s_w[1][tid] = wx1 * wy0 * vx1 * vy0;
        s_w[2][tid] = wx0 * wy1 * vx0 * vy1;
        s_w[3][tid] = wx1 * wy1 * vx1 * vy1;

        s_off[0][tid] = cy0 * W + cx0;
        s_off[1][tid] = cy0 * W + cx1;
        s_off[2][tid] = cy1 * W + cx0;
        s_off[3][tid] = cy1 * W + cx1;
    }
    __syncthreads();

    int pl = tid >> 3;                 // 0..31 -> pixels pl and pl+32
    int cg = tid & 7;                  // channel-group (0..7)

#pragma unroll
    for (int half = 0; half < 2; ++half) {
        int pp = pl + half * 32;
        float a0 = 0.f, a1 = 0.f, a2 = 0.f, a3 = 0.f;
#pragma unroll
        for (int k = 0; k < 4; ++k) {
            const float4* line = (const float4*)(g_xt + (size_t)s_off[k][pp] * C);
            float4 v = __ldg(line + cg);
            float  w = s_w[k][pp];
            a0 += w * v.x;
            a1 += w * v.y;
            a2 += w * v.z;
            a3 += w * v.w;
        }
        int c0 = cg * 4;
        s_out[pp][c0 + 0] = a0;
        s_out[pp][c0 + 1] = a1;
        s_out[pp][c0 + 2] = a2;
        s_out[pp][c0 + 3] = a3;
    }
    __syncthreads();

    // NCHW writeback: warp w handles channels 4w..4w+3 over 64 pixels
    int lane = tid & 31;
    int wid  = tid >> 5;
#pragma unroll
    for (int i = 0; i < 4; ++i) {
        int c = wid * 4 + i;
#pragma unroll
        for (int half = 0; half < 2; ++half) {
            __stcs(out + (size_t)c * HW + p0 + half * 32 + lane,
                   s_out[half * 32 + lane][c]);
        }
    }
}

extern "C" void kernel_launch(void* const* d_in, const int* in_sizes, int n_in,
                              void* d_out, int out_size)
{
    const float* flow = (const float*)d_in[0];   // [1,2,H,W]
    const float* x    = (const float*)d_in[1];   // [1,C,H,W]
    float* out        = (float*)d_out;           // [1,C,H,W]

    (void)in_sizes; (void)n_in; (void)out_size;

    transpose_kernel<<<HW / 128, 256>>>(x);
    warp_bilinear_coop_kernel<<<HW / 64, 256>>>(flow, out);
}

// round 5
// speedup vs baseline: 3.0115x; 1.2673x over previous
#include <cuda_runtime.h>
#include <cuda_fp16.h>
#include <cstdint>

// STN flow-relative bilinear warp, two-pass with fp16 NHWC scratch:
//   pass 1: NCHW f32 -> NHWC fp16 scratch (swizzled smem transpose)
//   pass 2: cooperative gather: 4 lanes/pixel, uint4 = 8 halves per corner,
//           fp32 weights + accumulation, NCHW f32 output.

static constexpr int H  = 1024;
static constexpr int W  = 1024;
static constexpr int C  = 32;
static constexpr int HW = H * W;

// 64 MB scratch: x transposed to [H*W][C] in fp16 (fits in L2)
__device__ __half g_xt[(size_t)HW * C];

// ---------------- pass 1: NCHW -> NHWC transpose + f32->fp16 ----------------
// Block: 256 threads, tile = 128 pixels x 32 channels.
__device__ __forceinline__ int sw_addr(int c, int px) {
    return c * 128 + 4 * ((px >> 2) ^ (c >> 2)) + (px & 3);
}

__global__ __launch_bounds__(256) void transpose_kernel(const float* __restrict__ x)
{
    __shared__ float s[32 * 128];

    int tid = threadIdx.x;
    int p0  = blockIdx.x * 128;

    // phase 1: read NCHW as float4 (coalesced, streaming), STS.128 swizzled
#pragma unroll
    for (int i = 0; i < 4; ++i) {
        int j   = i * 256 + tid;
        int c   = j >> 5;          // 0..31
        int pxg = j & 31;          // quad index 0..31
        float4 v = __ldcs((const float4*)(x + (size_t)c * HW + p0 + 4 * pxg));
        *(float4*)(s + c * 128 + 4 * (pxg ^ (c >> 2))) = v;
    }
    __syncthreads();

    // phase 2: gather 4 channels per thread (conflict-free), convert to fp16,
    // write uint2 (8B) NHWC -> warp writes 256B contiguous
#pragma unroll
    for (int i = 0; i < 4; ++i) {
        int j  = i * 256 + tid;
        int pl = j >> 3;           // pixel 0..127
        int cg = j & 7;            // channel group 0..7 (4 channels)
        __half2 h0 = __floats2half2_rn(s[sw_addr(4 * cg + 0, pl)],
                                       s[sw_addr(4 * cg + 1, pl)]);
        __half2 h1 = __floats2half2_rn(s[sw_addr(4 * cg + 2, pl)],
                                       s[sw_addr(4 * cg + 3, pl)]);
        uint2 v;
        v.x = *(const unsigned int*)&h0;
        v.y = *(const unsigned int*)&h1;
        *(uint2*)(g_xt + (size_t)(p0 + pl) * C + 4 * cg) = v;
    }
}

// ---------------- pass 2: bilinear warp from fp16 NHWC ----------------
// Block = 256 threads, 128 pixels. Thread = (pixel, channel-octet), 2 pixels each.
__global__ __launch_bounds__(256) void warp_bilinear_coop_kernel(
    const float* __restrict__ flow,
    float* __restrict__ out)
{
    __shared__ int   s_off[4][128];
    __shared__ float s_w[4][128];
    __shared__ float s_out[128][33];

    int tid = threadIdx.x;
    int p0  = blockIdx.x * 128;

    if (tid < 128) {
        int p  = p0 + tid;
        int px = p & (W - 1);
        int py = p >> 10;              // W == 1024

        float fx = flow[p];
        float fy = flow[HW + p];

        // Match reference math exactly (normalize + unnormalize round-trip)
        float gx = (fx + (float)px) * (2.0f / (float)(W - 1)) - 1.0f;
        float gy = (fy + (float)py) * (2.0f / (float)(H - 1)) - 1.0f;
        float ix = ((gx + 1.0f) * (float)W - 1.0f) * 0.5f;
        float iy = ((gy + 1.0f) * (float)H - 1.0f) * 0.5f;

        float x0f = floorf(ix);
        float y0f = floorf(iy);
        float wx1 = ix - x0f;
        float wy1 = iy - y0f;
        float wx0 = 1.0f - wx1;
        float wy0 = 1.0f - wy1;

        int x0 = (int)x0f;
        int y0 = (int)y0f;
        int x1 = x0 + 1;
        int y1 = y0 + 1;

        float vx0 = (x0 >= 0 && x0 < W) ? 1.0f : 0.0f;
        float vx1 = (x1 >= 0 && x1 < W) ? 1.0f : 0.0f;
        float vy0 = (y0 >= 0 && y0 < H) ? 1.0f : 0.0f;
        float vy1 = (y1 >= 0 && y1 < H) ? 1.0f : 0.0f;

        int cx0 = min(max(x0, 0), W - 1);
        int cx1 = min(max(x1, 0), W - 1);
        int cy0 = min(max(y0, 0), H - 1);
        int cy1 = min(max(y1, 0), H - 1);

        s_w[0][tid] = wx0 * wy0 * vx0 * vy0;
        s_w[1][tid] = wx1 * wy0 * vx1 * vy0;
        s_w[2][tid] = wx0 * wy1 * vx0 * vy1;
        s_w[3][tid] = wx1 * wy1 * vx1 * vy1;

        s_off[0][tid] = cy0 * W + cx0;
        s_off[1][tid] = cy0 * W + cx1;
        s_off[2][tid] = cy1 * W + cx0;
        s_off[3][tid] = cy1 * W + cx1;
    }
    __syncthreads();

    int pl = tid >> 2;                 // 0..63 -> pixels pl and pl+64
    int cg = tid & 3;                  // channel octet (0..3), 8 halves each

#pragma unroll
    for (int half = 0; half < 2; ++half) {
        int pp = pl + half * 64;
        float a0 = 0.f, a1 = 0.f, a2 = 0.f, a3 = 0.f;
        float a4 = 0.f, a5 = 0.f, a6 = 0.f, a7 = 0.f;
#pragma unroll
        for (int k = 0; k < 4; ++k) {
            const uint4* line = (const uint4*)(g_xt + (size_t)s_off[k][pp] * C);
            uint4 v = __ldg(line + cg);          // 8 halves = 8 channels
            float w = s_w[k][pp];
            float2 f0 = __half22float2(*(const __half2*)&v.x);
            float2 f1 = __half22float2(*(const __half2*)&v.y);
            float2 f2 = __half22float2(*(const __half2*)&v.z);
            float2 f3 = __half22float2(*(const __half2*)&v.w);
            a0 += w * f0.x;  a1 += w * f0.y;
            a2 += w * f1.x;  a3 += w * f1.y;
            a4 += w * f2.x;  a5 += w * f2.y;
            a6 += w * f3.x;  a7 += w * f3.y;
        }
        int c0 = cg * 8;
        s_out[pp][c0 + 0] = a0;   // bank = (pp + 8*cg + j) mod 32: conflict-free
        s_out[pp][c0 + 1] = a1;
        s_out[pp][c0 + 2] = a2;
        s_out[pp][c0 + 3] = a3;
        s_out[pp][c0 + 4] = a4;
        s_out[pp][c0 + 5] = a5;
        s_out[pp][c0 + 6] = a6;
        s_out[pp][c0 + 7] = a7;
    }
    __syncthreads();

    // NCHW writeback: warp w handles channels 4w..4w+3 over 128 pixels
    int lane = tid & 31;
    int wid  = tid >> 5;
#pragma unroll
    for (int i = 0; i < 4; ++i) {
        int c = wid * 4 + i;
#pragma unroll
        for (int q = 0; q < 4; ++q) {
            __stcs(out + (size_t)c * HW + p0 + q * 32 + lane,
                   s_out[q * 32 + lane][c]);
        }
    }
}

extern "C" void kernel_launch(void* const* d_in, const int* in_sizes, int n_in,
                              void* d_out, int out_size)
{
    const float* flow = (const float*)d_in[0];   // [1,2,H,W]
    const float* x    = (const float*)d_in[1];   // [1,C,H,W]
    float* out        = (float*)d_out;           // [1,C,H,W]

    (void)in_sizes; (void)n_in; (void)out_size;

    transpose_kernel<<<HW / 128, 256>>>(x);
    warp_bilinear_coop_kernel<<<HW / 128, 256>>>(flow, out);
}